// round 17
// baseline (speedup 1.0000x reference)
#include <cuda_runtime.h>
#include <cuda_fp16.h>
#include <cstdint>

#define IN_F 256
#define OUT_F 128
#define MAX_NODES 100000
#define BM 128
#define BN 128
#define BK 32
#define EPW 24   // edges per warp per grid pass (12 per 16-lane half)

__device__ __half g_hh[(size_t)MAX_NODES * OUT_F];

__device__ __forceinline__ uint32_t f2tf32u(float x) {
    uint32_t o;
    asm("cvt.rna.tf32.f32 %0, %1;" : "=r"(o) : "f"(x));
    return o;
}

__device__ __forceinline__ void mma_tf32(float* c, const uint32_t* a,
                                         uint32_t b0, uint32_t b1) {
    asm volatile(
        "mma.sync.aligned.m16n8k8.row.col.f32.tf32.tf32.f32 "
        "{%0,%1,%2,%3}, {%4,%5,%6,%7}, {%8,%9}, {%0,%1,%2,%3};\n"
        : "+f"(c[0]), "+f"(c[1]), "+f"(c[2]), "+f"(c[3])
        : "r"(a[0]), "r"(a[1]), "r"(a[2]), "r"(a[3]), "r"(b0), "r"(b1));
}

__device__ __forceinline__ void cp_async16(void* smem_dst, const void* gsrc, int src_bytes) {
    uint32_t daddr = (uint32_t)__cvta_generic_to_shared(smem_dst);
    asm volatile("cp.async.ca.shared.global [%0], [%1], 16, %2;\n"
                 :: "r"(daddr), "l"(gsrc), "r"(src_bytes));
}
__device__ __forceinline__ void cp_commit() {
    asm volatile("cp.async.commit_group;\n" ::: "memory");
}
template <int N>
__device__ __forceinline__ void cp_wait() {
    asm volatile("cp.async.wait_group %0;\n" :: "n"(N) : "memory");
}

// ---------------------------------------------------------------------------
// GEMM: tf32 mma.sync. A via cp.async (fp32, cvt at frag load). B via
// LDG -> cvt.rna at STS -> smem holds tf32 BITS; hot loop reads raw uint.
// Removes 48 of 64 B-cvt warp-instrs per kt from the hot loop. Identical
// bits enter mma -> numerics unchanged.
// ---------------------------------------------------------------------------
__global__ __launch_bounds__(256, 2) void gemm_tf32_kernel(
    const float* __restrict__ A,   // [M, 256]
    const float* __restrict__ Bw,  // [256, 128]
    float* __restrict__ C,         // [M, 128]
    int M)
{
    __shared__ float As[2][BM][BK + 4];
    __shared__ unsigned Bs[2][BK][BN + 8];   // tf32 bits

    const int tid = threadIdx.x;
    const int wid = tid >> 5;
    const int lane = tid & 31;
    const int g = lane >> 2;
    const int t4 = lane & 3;
    const int warp_m = wid & 3;
    const int warp_n = wid >> 2;
    const int row0 = blockIdx.x * BM;

    float c[2][8][4];
#pragma unroll
    for (int mt = 0; mt < 2; mt++)
#pragma unroll
        for (int nt = 0; nt < 8; nt++)
#pragma unroll
            for (int i = 0; i < 4; i++) c[mt][nt][i] = 0.0f;

    const int NITER = IN_F / BK;  // 8

    auto prefetchA = [&](int kt, int buf) {
        const int k0 = kt * BK;
#pragma unroll
        for (int t = 0; t < 4; t++) {
            int idx = tid + t * 256;
            int ar = idx >> 3;
            int ac = idx & 7;
            int grow = row0 + ar;
            int ok = (grow < M) ? 16 : 0;
            int gc = (grow < M) ? grow : 0;
            cp_async16(&As[buf][ar][ac * 4],
                       A + (size_t)gc * IN_F + k0 + ac * 4, ok);
        }
        cp_commit();
    };

    uint4 breg[4];   // staging for B stage kt (raw fp32 bits)
    auto ldgB = [&](int kt) {
        const int k0 = kt * BK;
#pragma unroll
        for (int t = 0; t < 4; t++) {
            int idx = tid + t * 256;
            int br = idx >> 5;
            int bc = idx & 31;
            breg[t] = *reinterpret_cast<const uint4*>(
                Bw + (size_t)(k0 + br) * OUT_F + bc * 4);
        }
    };
    auto stsB = [&](int buf) {
#pragma unroll
        for (int t = 0; t < 4; t++) {
            int idx = tid + t * 256;
            int br = idx >> 5;
            int bc = idx & 31;
            uint4 o;
            o.x = f2tf32u(__uint_as_float(breg[t].x));
            o.y = f2tf32u(__uint_as_float(breg[t].y));
            o.z = f2tf32u(__uint_as_float(breg[t].z));
            o.w = f2tf32u(__uint_as_float(breg[t].w));
            *reinterpret_cast<uint4*>(&Bs[buf][br][bc * 4]) = o;
        }
    };

    prefetchA(0, 0);
    ldgB(0);

    for (int kt = 0; kt < NITER; kt++) {
        const int buf = kt & 1;
        stsB(buf);          // B(kt) -> its buffer (prev compute on other buf done
                            //   before last iter's barrier; safe)
        cp_wait<0>();       // A(kt) complete
        __syncthreads();    // A(kt) + B(kt) visible to all
        if (kt + 1 < NITER) {
            prefetchA(kt + 1, (kt + 1) & 1);
            ldgB(kt + 1);   // latency hidden under compute(kt)
        }

#pragma unroll
        for (int k8 = 0; k8 < 4; k8++) {
            const int k = k8 * 8;
            uint32_t afr[2][4];
#pragma unroll
            for (int mt = 0; mt < 2; mt++) {
                int rb = warp_m * 32 + mt * 16;
                afr[mt][0] = f2tf32u(As[buf][rb + g][k + t4]);
                afr[mt][1] = f2tf32u(As[buf][rb + g + 8][k + t4]);
                afr[mt][2] = f2tf32u(As[buf][rb + g][k + t4 + 4]);
                afr[mt][3] = f2tf32u(As[buf][rb + g + 8][k + t4 + 4]);
            }
#pragma unroll
            for (int nt = 0; nt < 8; nt++) {
                int nb = warp_n * 64 + nt * 8 + g;
                uint32_t b0 = Bs[buf][k + t4][nb];
                uint32_t b1 = Bs[buf][k + t4 + 4][nb];
                mma_tf32(c[0][nt], afr[0], b0, b1);
                mma_tf32(c[1][nt], afr[1], b0, b1);
            }
        }
    }

    // Epilogue: fp32 to C, fp16 to g_hh.
#pragma unroll
    for (int mt = 0; mt < 2; mt++) {
#pragma unroll
        for (int half = 0; half < 2; half++) {
            int row = row0 + warp_m * 32 + mt * 16 + g + half * 8;
            if (row < M) {
#pragma unroll
                for (int nt = 0; nt < 8; nt++) {
                    int col = warp_n * 64 + nt * 8 + 2 * t4;
                    float x = c[mt][nt][half * 2];
                    float y = c[mt][nt][half * 2 + 1];
                    *reinterpret_cast<float2*>(C + (size_t)row * OUT_F + col) =
                        make_float2(x, y);
                    __half2 hv = __floats2half2_rn(x, y);
                    *reinterpret_cast<__half2*>(g_hh + (size_t)row * OUT_F + col) = hv;
                }
            }
        }
    }
}

// ---------------------------------------------------------------------------
// Edge kernel (R16 form + occupancy push to 7 blocks/SM): per warp 24
// consecutive edges; coalesced index load + shuffle distribution; 16-lane
// half does 12 edges in 4 iters of 3 (MLP=6); butterfly reduce + park ->
// one coalesced 24-float store.
// ---------------------------------------------------------------------------
__device__ __forceinline__ float2 h2f(unsigned w) {
    __half2 b = *reinterpret_cast<__half2*>(&w);
    return __half22float2(b);
}

__device__ __forceinline__ float edge_dot(uint4 hu, uint4 hv,
                                          float4 a0, float4 a1) {
    float2 u0 = h2f(hu.x), u1 = h2f(hu.y), u2 = h2f(hu.z), u3 = h2f(hu.w);
    float2 v0 = h2f(hv.x), v1 = h2f(hv.y), v2 = h2f(hv.z), v3 = h2f(hv.w);
    return fabsf(u0.x - v0.x) * a0.x
         + fabsf(u0.y - v0.y) * a0.y
         + fabsf(u1.x - v1.x) * a0.z
         + fabsf(u1.y - v1.y) * a0.w
         + fabsf(u2.x - v2.x) * a1.x
         + fabsf(u2.y - v2.y) * a1.y
         + fabsf(u3.x - v3.x) * a1.z
         + fabsf(u3.y - v3.y) * a1.w;
}

__global__ __launch_bounds__(256, 7) void edge_kernel(
    const int* __restrict__ edge,         // [2,E] int32
    const float* __restrict__ a,          // [128]
    float* __restrict__ ew,               // [E]
    int E)
{
    const int lane = threadIdx.x & 31;
    const int half_id = lane >> 4;
    const int l16 = lane & 15;

    const float4 a0 = *(reinterpret_cast<const float4*>(a) + l16 * 2);
    const float4 a1 = *(reinterpret_cast<const float4*>(a) + l16 * 2 + 1);

    const int warps_total = (gridDim.x * blockDim.x) >> 5;
    const int warp = (blockIdx.x * blockDim.x + threadIdx.x) >> 5;

    for (int base = warp * EPW; base < E; base += warps_total * EPW) {
        int u = 0, v = 0;
        int gidx = base + lane;
        if (lane < EPW && gidx < E) {
            u = edge[gidx];
            v = edge[(size_t)E + gidx];
        }

        float out = 0.0f;

#pragma unroll 1
        for (int j3 = 0; j3 < 4; j3++) {
            const int s0 = half_id * 12 + j3 * 3;

            int ua = __shfl_sync(0xFFFFFFFFu, u, s0);
            int va = __shfl_sync(0xFFFFFFFFu, v, s0);
            int ub = __shfl_sync(0xFFFFFFFFu, u, s0 + 1);
            int vb = __shfl_sync(0xFFFFFFFFu, v, s0 + 1);
            int uc = __shfl_sync(0xFFFFFFFFu, u, s0 + 2);
            int vc = __shfl_sync(0xFFFFFFFFu, v, s0 + 2);

            uint4 hua = *(reinterpret_cast<const uint4*>(g_hh + (size_t)ua * OUT_F) + l16);
            uint4 hva = *(reinterpret_cast<const uint4*>(g_hh + (size_t)va * OUT_F) + l16);
            uint4 hub = *(reinterpret_cast<const uint4*>(g_hh + (size_t)ub * OUT_F) + l16);
            uint4 hvb = *(reinterpret_cast<const uint4*>(g_hh + (size_t)vb * OUT_F) + l16);
            uint4 huc = *(reinterpret_cast<const uint4*>(g_hh + (size_t)uc * OUT_F) + l16);
            uint4 hvc = *(reinterpret_cast<const uint4*>(g_hh + (size_t)vc * OUT_F) + l16);

            float s1 = edge_dot(hua, hva, a0, a1);
            float s2 = edge_dot(hub, hvb, a0, a1);
            float s3 = edge_dot(huc, hvc, a0, a1);

#pragma unroll
            for (int off = 8; off > 0; off >>= 1) {
                s1 += __shfl_xor_sync(0xFFFFFFFFu, s1, off, 16);
                s2 += __shfl_xor_sync(0xFFFFFFFFu, s2, off, 16);
                s3 += __shfl_xor_sync(0xFFFFFFFFu, s3, off, 16);
            }

            const int j0 = j3 * 3;
            if (l16 == j0)     out = s1;
            if (l16 == j0 + 1) out = s2;
            if (l16 == j0 + 2) out = s3;
        }

        const int off = half_id * 12 + l16;
        if (l16 < 12 && base + off < E)
            ew[base + off] = fmaxf(out, 0.0f);
    }
}

extern "C" void kernel_launch(void* const* d_in, const int* in_sizes, int n_in,
                              void* d_out, int out_size)
{
    const float* inputs = (const float*)d_in[0];
    const int* edge     = (const int*)d_in[1];
    const float* weight = (const float*)d_in[2];
    const float* a      = (const float*)d_in[3];

    int M = in_sizes[0] / IN_F;        // 100000
    int E = in_sizes[1] / 2;           // 1600000

    float* h  = (float*)d_out;                       // [M,128]
    float* ew = (float*)d_out + (size_t)M * OUT_F;   // [E]

    int gemm_blocks = (M + BM - 1) / BM;             // 782
    gemm_tf32_kernel<<<gemm_blocks, 256>>>(inputs, weight, h, M);

    edge_kernel<<<4096, 256>>>(edge, a, ew, E);
}